// round 7
// baseline (speedup 1.0000x reference)
#include <cuda_runtime.h>
#include <cuda_fp16.h>
#include <cstdint>

// Problem constants (fixed by the reference)
#define NNODES 50000
#define NREL   8
#define DIM    128
#define NEDGES 800000
#define NZ     9                       // 8 relations + root path
#define MTILE  128
#define NRB    ((NNODES + MTILE - 1) / MTILE)   // 391 row blocks
#define SEG    (NREL * NNODES)         // 400000
#define NSCAN_BLK ((SEG + 511) / 512)  // 782

// smem tiles viewed as uint32 (half2). 16 u32/row padded to 20 -> conflict-free.
#define TSTR32 20
#define A_TILE_U32 (MTILE * TSTR32)
#define B_TILE_U32 (MTILE * TSTR32)

// ---------------- scratch (static device globals; no allocation) ----------------
__device__ __half g_Y16[(size_t)NREL * NNODES * DIM]; // per-relation transformed features (fp16)
__device__ float  g_acc[(size_t)NNODES * DIM];        // root-path fp32 accumulator (both layers)
__device__ __half g_A16[(size_t)NNODES * DIM];        // fp16 GEMM input
__device__ __half g_WH[2 * NZ * DIM * DIM];           // fp16 transposed weights [z][n][k]
__device__ int    g_cnt[SEG];
__device__ int    g_incl[SEG];
__device__ int    g_off[SEG + 1];
__device__ int    g_cursor[SEG];
__device__ int    g_binh[NEDGES];
__device__ int    g_bsum[1024];

// ---------------- helpers ----------------
__device__ __forceinline__ void mma_f16(float* c, const uint32_t* a, const uint32_t* b) {
    asm volatile(
        "mma.sync.aligned.m16n8k16.row.col.f32.f16.f16.f32 "
        "{%0,%1,%2,%3}, {%4,%5,%6,%7}, {%8,%9}, {%0,%1,%2,%3};"
        : "+f"(c[0]), "+f"(c[1]), "+f"(c[2]), "+f"(c[3])
        : "r"(a[0]), "r"(a[1]), "r"(a[2]), "r"(a[3]), "r"(b[0]), "r"(b[1]));
}
__device__ __forceinline__ void cp_async16(uint32_t daddr, const void* src, int srcbytes) {
    asm volatile("cp.async.cg.shared.global [%0], [%1], 16, %2;"
                 :: "r"(daddr), "l"(src), "r"(srcbytes));
}
#define CP_COMMIT() asm volatile("cp.async.commit_group;" ::: "memory")
#define CP_WAIT1()  asm volatile("cp.async.wait_group 1;" ::: "memory")
#define CP_WAIT0()  asm volatile("cp.async.wait_group 0;" ::: "memory")

// ---------------- setup / binning kernels ----------------
__global__ void k_zero_cnt(int* __restrict__ cnt, int n) {
    int i = blockIdx.x * blockDim.x + threadIdx.x;
    if (i < n) cnt[i] = 0;
}
__global__ void k_count(const int* __restrict__ r, const int* __restrict__ t,
                        int* __restrict__ cnt, int E) {
    int e = blockIdx.x * blockDim.x + threadIdx.x;
    if (e < E) atomicAdd(&cnt[r[e] * NNODES + t[e]], 1);
}
__global__ void k_scan1(const int* __restrict__ cnt, int* __restrict__ incl,
                        int* __restrict__ bsum, int n) {
    __shared__ int sm[512];
    int tid = threadIdx.x;
    int gid = blockIdx.x * 512 + tid;
    sm[tid] = (gid < n) ? cnt[gid] : 0;
    __syncthreads();
#pragma unroll
    for (int d = 1; d < 512; d <<= 1) {
        int add = (tid >= d) ? sm[tid - d] : 0;
        __syncthreads();
        sm[tid] += add;
        __syncthreads();
    }
    if (gid < n) incl[gid] = sm[tid];
    if (tid == 511) bsum[blockIdx.x] = sm[511];
}
__global__ void k_scan2(int* __restrict__ bsum, int nb) {
    __shared__ int sm[1024];
    int tid = threadIdx.x;
    sm[tid] = (tid < nb) ? bsum[tid] : 0;
    __syncthreads();
#pragma unroll
    for (int d = 1; d < 1024; d <<= 1) {
        int add = (tid >= d) ? sm[tid - d] : 0;
        __syncthreads();
        sm[tid] += add;
        __syncthreads();
    }
    if (tid < nb) bsum[tid] = sm[tid];
}
__global__ void k_scan3(const int* __restrict__ cnt, const int* __restrict__ incl,
                        const int* __restrict__ bsum, int* __restrict__ off,
                        int* __restrict__ cursor, int n) {
    int gid = blockIdx.x * 512 + threadIdx.x;
    if (gid >= n) return;
    int base = (blockIdx.x > 0) ? bsum[blockIdx.x - 1] : 0;
    int ex = base + incl[gid] - cnt[gid];
    off[gid] = ex;
    cursor[gid] = ex;
    if (gid == n - 1) off[n] = base + incl[gid];
}
__global__ void k_bin(const int* __restrict__ h, const int* __restrict__ r,
                      const int* __restrict__ t, int* __restrict__ cursor,
                      int* __restrict__ binh, int E) {
    int e = blockIdx.x * blockDim.x + threadIdx.x;
    if (e >= E) return;
    int seg = r[e] * NNODES + t[e];
    int pos = atomicAdd(&cursor[seg], 1);
    binh[pos] = h[e];
}

// WH for BOTH layers in one launch: [layer][z][n][k] = fp16 of W[k][n] (transposed)
__global__ void k_wt2(const float* __restrict__ W1, const float* __restrict__ root1,
                      const float* __restrict__ W2, const float* __restrict__ root2,
                      __half* __restrict__ dst) {
    int idx = blockIdx.x * blockDim.x + threadIdx.x;
    if (idx >= 2 * NZ * DIM * DIM) return;
    int zz = idx >> 14;              // 0..17
    int layer = zz / NZ, z = zz % NZ;
    int rem = idx & 16383;
    int n = rem >> 7, k = rem & 127;
    const float* src = (z < 8) ? ((layer ? W2 : W1) + ((size_t)z << 14))
                               : (layer ? root2 : root1);
    dst[idx] = __float2half_rn(src[k * DIM + n]);
}

__global__ void k_cvt16(const float2* __restrict__ in, uint32_t* __restrict__ out, int n2) {
    int i = blockIdx.x * blockDim.x + threadIdx.x;
    if (i < n2) {
        float2 v = in[i];
        __half2 hv = __floats2half2_rn(v.x, v.y);
        out[i] = *(uint32_t*)&hv;
    }
}

// ---------------- fp16 mma.sync GEMM: Y_z = X @ W_z, z==8 -> fp32 acc + bias ----------------
__global__ __launch_bounds__(256, 2) void k_gemm_mma(
    const __half* __restrict__ X, const __half* __restrict__ WH,
    const float* __restrict__ bias, __half* __restrict__ Y,
    float* __restrict__ acc, int Nn)
{
    __shared__ uint32_t As[2][A_TILE_U32];
    __shared__ uint32_t Bs[2][B_TILE_U32];

    const int tid = threadIdx.x;
    const int wid = tid >> 5;
    const int lane = tid & 31;
    const int g = lane >> 2;
    const int q = lane & 3;
    const int warp_m = wid & 3;
    const int warp_n = wid >> 2;
    const int z = blockIdx.y;
    const int row0 = blockIdx.x * MTILE;

    const __half* Bsrc = WH + ((size_t)z << 14);

    float cfrag[2][8][4];
#pragma unroll
    for (int mt = 0; mt < 2; mt++)
#pragma unroll
        for (int nt = 0; nt < 8; nt++)
#pragma unroll
            for (int i = 0; i < 4; i++) cfrag[mt][nt][i] = 0.0f;

    auto load_chunk = [&](int buf, int k0) {
        uint32_t abase = (uint32_t)__cvta_generic_to_shared(&As[buf][0]);
        uint32_t bbase = (uint32_t)__cvta_generic_to_shared(&Bs[buf][0]);
#pragma unroll
        for (int l = 0; l < 2; l++) {
            int lin = tid + 256 * l;
            int row = lin >> 2, seg = lin & 3;
            int gr = row0 + row;
            int ok = (gr < Nn) ? 16 : 0;
            int grc = (gr < Nn) ? gr : (Nn - 1);
            cp_async16(abase + (uint32_t)(row * TSTR32 + seg * 4) * 4,
                       X + (size_t)grc * DIM + k0 + seg * 8, ok);
        }
#pragma unroll
        for (int l = 0; l < 2; l++) {
            int lin = tid + 256 * l;
            int row = lin >> 2, seg = lin & 3;
            cp_async16(bbase + (uint32_t)(row * TSTR32 + seg * 4) * 4,
                       Bsrc + (size_t)row * DIM + k0 + seg * 8, 16);
        }
        CP_COMMIT();
    };

    load_chunk(0, 0);

#pragma unroll
    for (int c = 0; c < 4; c++) {
        if (c < 3) load_chunk((c + 1) & 1, (c + 1) * 32);
        if (c < 3) CP_WAIT1(); else CP_WAIT0();
        __syncthreads();

        const uint32_t* A_ = As[c & 1];
        const uint32_t* B_ = Bs[c & 1];
        const int ar = warp_m * 32 + g;
        const int bn = warp_n * 64 + g;

#pragma unroll
        for (int ks = 0; ks < 2; ks++) {
            const int ko = ks * 8 + q;
            uint32_t a[2][4];
#pragma unroll
            for (int mt = 0; mt < 2; mt++) {
                int base = (ar + mt * 16) * TSTR32 + ko;
                a[mt][0] = A_[base];
                a[mt][1] = A_[base + 8 * TSTR32];
                a[mt][2] = A_[base + 4];
                a[mt][3] = A_[base + 8 * TSTR32 + 4];
            }
            uint32_t b[8][2];
#pragma unroll
            for (int nt = 0; nt < 8; nt++) {
                int base = (bn + nt * 8) * TSTR32 + ko;
                b[nt][0] = B_[base];
                b[nt][1] = B_[base + 4];
            }
#pragma unroll
            for (int mt = 0; mt < 2; mt++)
#pragma unroll
                for (int nt = 0; nt < 8; nt++)
                    mma_f16(cfrag[mt][nt], a[mt], b[nt]);
        }
        __syncthreads();
    }

    if (z < 8) {
        __half* C = Y + (size_t)z * Nn * DIM;
#pragma unroll
        for (int mt = 0; mt < 2; mt++)
#pragma unroll
            for (int half_ = 0; half_ < 2; half_++) {
                int row = row0 + warp_m * 32 + mt * 16 + half_ * 8 + g;
                if (row >= Nn) continue;
#pragma unroll
                for (int nt = 0; nt < 8; nt++) {
                    int col = warp_n * 64 + nt * 8 + 2 * q;
                    __half2 hv = __floats2half2_rn(cfrag[mt][nt][half_ * 2 + 0],
                                                   cfrag[mt][nt][half_ * 2 + 1]);
                    *(uint32_t*)&C[(size_t)row * DIM + col] = *(uint32_t*)&hv;
                }
            }
    } else {
#pragma unroll
        for (int mt = 0; mt < 2; mt++)
#pragma unroll
            for (int half_ = 0; half_ < 2; half_++) {
                int row = row0 + warp_m * 32 + mt * 16 + half_ * 8 + g;
                if (row >= Nn) continue;
#pragma unroll
                for (int nt = 0; nt < 8; nt++) {
                    int col = warp_n * 64 + nt * 8 + 2 * q;
                    float2 v;
                    v.x = cfrag[mt][nt][half_ * 2 + 0] + bias[col];
                    v.y = cfrag[mt][nt][half_ * 2 + 1] + bias[col + 1];
                    *(float2*)&acc[(size_t)row * DIM + col] = v;
                }
            }
    }
}

// ---------------- aggregation: one warp per target node, atomic-free ----------------
// Two edges in flight per warp (half-warp x uint4 covers a 256B fp16 row).
// MODE 0: out = relu(acc + sum_r mean) -> fp16 A16.
// MODE 1: final layer -> block-reduced column mean accumulated into out[128].
template <int MODE>
__global__ __launch_bounds__(256) void k_agg(
    const __half* __restrict__ Y, const int* __restrict__ off,
    const int* __restrict__ binh, const float* __restrict__ accin,
    uint4* __restrict__ out16, float* __restrict__ outf)
{
    __shared__ float bsum[8][DIM];
    const int wid = threadIdx.x >> 5;
    const int lane = threadIdx.x & 31;
    const int t = blockIdx.x * 8 + wid;           // NNODES % 8 == 0 -> always valid
    const int hf = lane >> 4;                      // 0/1: which edge of the pair
    const int l16 = lane & 15;                     // 16B chunk within row

    // parallel offset preload: lane r in [0,8) -> start, lane 16+r -> end
    int o = 0;
    if (lane < 8)                    o = __ldg(&off[lane * NNODES + t]);
    else if (lane >= 16 && lane < 24) o = __ldg(&off[(lane - 16) * NNODES + t + 1]);

    float a[8];
    if (hf == 0) {
        float4 lo = *(const float4*)(accin + (size_t)t * DIM + l16 * 8);
        float4 hi = *(const float4*)(accin + (size_t)t * DIM + l16 * 8 + 4);
        a[0] = lo.x; a[1] = lo.y; a[2] = lo.z; a[3] = lo.w;
        a[4] = hi.x; a[5] = hi.y; a[6] = hi.z; a[7] = hi.w;
    } else {
#pragma unroll
        for (int j = 0; j < 8; j++) a[j] = 0.0f;
    }

#pragma unroll
    for (int rr = 0; rr < NREL; rr++) {
        int s = __shfl_sync(0xffffffff, o, rr);
        int e = __shfl_sync(0xffffffff, o, 16 + rr);
        if (e > s) {
            const __half* Yr = Y + (size_t)rr * NNODES * DIM;
            float p[8];
#pragma unroll
            for (int j = 0; j < 8; j++) p[j] = 0.0f;
            for (int i = s + hf; i < e; i += 2) {
                int hh = __ldg(&binh[i]);
                uint4 v = ((const uint4*)(Yr + (size_t)hh * DIM))[l16];
                __half2* hp = (__half2*)&v;
                float2 f0 = __half22float2(hp[0]);
                float2 f1 = __half22float2(hp[1]);
                float2 f2 = __half22float2(hp[2]);
                float2 f3 = __half22float2(hp[3]);
                p[0] += f0.x; p[1] += f0.y; p[2] += f1.x; p[3] += f1.y;
                p[4] += f2.x; p[5] += f2.y; p[6] += f3.x; p[7] += f3.y;
            }
            float w = 1.0f / (float)(e - s);
#pragma unroll
            for (int j = 0; j < 8; j++) a[j] += p[j] * w;
        }
    }
    // merge the two half-warps (lanes L and L+16 hold the same columns)
#pragma unroll
    for (int j = 0; j < 8; j++) a[j] += __shfl_xor_sync(0xffffffff, a[j], 16);

    if (MODE == 0) {
        if (hf == 0) {
            __half2 h0 = __floats2half2_rn(fmaxf(a[0], 0.f), fmaxf(a[1], 0.f));
            __half2 h1 = __floats2half2_rn(fmaxf(a[2], 0.f), fmaxf(a[3], 0.f));
            __half2 h2 = __floats2half2_rn(fmaxf(a[4], 0.f), fmaxf(a[5], 0.f));
            __half2 h3 = __floats2half2_rn(fmaxf(a[6], 0.f), fmaxf(a[7], 0.f));
            uint4 ov;
            ov.x = *(uint32_t*)&h0; ov.y = *(uint32_t*)&h1;
            ov.z = *(uint32_t*)&h2; ov.w = *(uint32_t*)&h3;
            out16[(size_t)t * (DIM / 8) + l16] = ov;
        }
    } else {
        if (hf == 0) {
#pragma unroll
            for (int j = 0; j < 8; j++) bsum[wid][l16 * 8 + j] = a[j];
        }
        __syncthreads();
        int c = threadIdx.x;
        if (c < DIM) {
            float s = 0.0f;
#pragma unroll
            for (int w2 = 0; w2 < 8; w2++) s += bsum[w2][c];
            atomicAdd(&outf[c], s * (1.0f / (float)NNODES));
        }
    }
}

__global__ void k_zero_out(float* __restrict__ out) { out[threadIdx.x] = 0.0f; }

// ---------------- launch ----------------
extern "C" void kernel_launch(void* const* d_in, const int* in_sizes, int n_in,
                              void* d_out, int out_size) {
    const int*   h     = (const int*)d_in[0];
    const int*   r     = (const int*)d_in[1];
    const int*   t     = (const int*)d_in[2];
    const float* x_emb = (const float*)d_in[3];
    const float* W1    = (const float*)d_in[4];
    const float* root1 = (const float*)d_in[5];
    const float* b1    = (const float*)d_in[6];
    const float* W2    = (const float*)d_in[7];
    const float* root2 = (const float*)d_in[8];
    const float* b2    = (const float*)d_in[9];
    float* out = (float*)d_out;

    __half *Y16, *A16, *WH;
    float *acc;
    int *cnt, *incl, *off, *cursor, *binh, *bsum;
    cudaGetSymbolAddress((void**)&Y16,    g_Y16);
    cudaGetSymbolAddress((void**)&acc,    g_acc);
    cudaGetSymbolAddress((void**)&A16,    g_A16);
    cudaGetSymbolAddress((void**)&WH,     g_WH);
    cudaGetSymbolAddress((void**)&cnt,    g_cnt);
    cudaGetSymbolAddress((void**)&incl,   g_incl);
    cudaGetSymbolAddress((void**)&off,    g_off);
    cudaGetSymbolAddress((void**)&cursor, g_cursor);
    cudaGetSymbolAddress((void**)&binh,   g_binh);
    cudaGetSymbolAddress((void**)&bsum,   g_bsum);

    const int E = NEDGES, Nn = NNODES;
    const int n2 = Nn * DIM / 2;
    dim3 ggrid(NRB, NZ);
    const int agg_blocks = Nn / 8;   // 6250

    // [0] weights (both layers), [1] input cvt, [2] zero counters
    k_wt2<<<(2 * NZ * DIM * DIM + 255) / 256, 256>>>(W1, root1, W2, root2, WH);
    k_cvt16<<<(n2 + 255) / 256, 256>>>((const float2*)x_emb, (uint32_t*)A16, n2);
    k_zero_cnt<<<(SEG + 255) / 256, 256>>>(cnt, SEG);

    // [3] layer-1 GEMM (profiled launch)
    k_gemm_mma<<<ggrid, 256>>>(A16, WH, b1, Y16, acc, Nn);

    // CSR build (independent of GEMM results)
    k_count<<<(E + 255) / 256, 256>>>(r, t, cnt, E);
    k_scan1<<<NSCAN_BLK, 512>>>(cnt, incl, bsum, SEG);
    k_scan2<<<1, 1024>>>(bsum, NSCAN_BLK);
    k_scan3<<<NSCAN_BLK, 512>>>(cnt, incl, bsum, off, cursor, SEG);
    k_bin<<<(E + 255) / 256, 256>>>(h, r, t, cursor, binh, E);

    // layer-1 aggregation -> relu -> fp16 A16
    k_agg<0><<<agg_blocks, 256>>>(Y16, off, binh, acc, (uint4*)A16, nullptr);

    // layer-2 GEMM + aggregation fused with final column mean
    k_gemm_mma<<<ggrid, 256>>>(A16, WH + (size_t)NZ * DIM * DIM, b2, Y16, acc, Nn);
    k_zero_out<<<1, DIM>>>(out);
    k_agg<1><<<agg_blocks, 256>>>(Y16, off, binh, acc, nullptr, out);
}

// round 8
// speedup vs baseline: 1.1793x; 1.1793x over previous
#include <cuda_runtime.h>
#include <cuda_fp16.h>
#include <cstdint>

// Problem constants (fixed by the reference)
#define NNODES 50000
#define NREL   8
#define DIM    128
#define NEDGES 800000
#define NZ     9                       // 8 relations + root path
#define MTILE  128
#define NRB    ((NNODES + MTILE - 1) / MTILE)   // 391 row blocks
#define SEG    (NREL * NNODES)         // 400000
#define NSCAN_BLK ((SEG + 511) / 512)  // 782

// full-K smem tiles viewed as u32 (half2): 64 u32/row padded to 68 -> conflict-free
// (bank of fragment load = (68*g + q) % 32 = (4g + q) % 32, bijective over the warp)
#define KSTR 68
#define A_SM (MTILE * KSTR)            // 8704 u32 = 34816 B
#define B_SM (MTILE * KSTR)
#define GEMM_SMEM ((A_SM + 2 * B_SM) * 4)   // 104448 B

// ---------------- scratch (static device globals; no allocation) ----------------
__device__ __half g_Y16[(size_t)NREL * NNODES * DIM]; // per-relation transformed features (fp16)
__device__ float  g_acc[(size_t)NNODES * DIM];        // root-path fp32 accumulator (both layers)
__device__ __half g_A16[(size_t)NNODES * DIM];        // fp16 GEMM input
__device__ __half g_WH[2 * NZ * DIM * DIM];           // fp16 transposed weights [layer][z][n][k]
__device__ int    g_cnt[SEG];
__device__ int    g_incl[SEG];
__device__ int    g_off[SEG + 1];
__device__ int    g_cursor[SEG];
__device__ int    g_binh[NEDGES];
__device__ int    g_bsum[1024];

// ---------------- helpers ----------------
__device__ __forceinline__ void mma_f16(float* c, const uint32_t* a, const uint32_t* b) {
    asm volatile(
        "mma.sync.aligned.m16n8k16.row.col.f32.f16.f16.f32 "
        "{%0,%1,%2,%3}, {%4,%5,%6,%7}, {%8,%9}, {%0,%1,%2,%3};"
        : "+f"(c[0]), "+f"(c[1]), "+f"(c[2]), "+f"(c[3])
        : "r"(a[0]), "r"(a[1]), "r"(a[2]), "r"(a[3]), "r"(b[0]), "r"(b[1]));
}
__device__ __forceinline__ void cp_async16(uint32_t daddr, const void* src, int srcbytes) {
    asm volatile("cp.async.cg.shared.global [%0], [%1], 16, %2;"
                 :: "r"(daddr), "l"(src), "r"(srcbytes));
}
#define CP_COMMIT() asm volatile("cp.async.commit_group;" ::: "memory")
#define CP_WAIT1()  asm volatile("cp.async.wait_group 1;" ::: "memory")
#define CP_WAIT0()  asm volatile("cp.async.wait_group 0;" ::: "memory")

// ---------------- setup / binning kernels ----------------
__global__ void k_zero_cnt(int* __restrict__ cnt, int n) {
    int i = blockIdx.x * blockDim.x + threadIdx.x;
    if (i < n) cnt[i] = 0;
}
__global__ void k_count(const int* __restrict__ r, const int* __restrict__ t,
                        int* __restrict__ cnt, int E) {
    int e = blockIdx.x * blockDim.x + threadIdx.x;
    if (e < E) atomicAdd(&cnt[r[e] * NNODES + t[e]], 1);
}
__global__ void k_scan1(const int* __restrict__ cnt, int* __restrict__ incl,
                        int* __restrict__ bsum, int n) {
    __shared__ int sm[512];
    int tid = threadIdx.x;
    int gid = blockIdx.x * 512 + tid;
    sm[tid] = (gid < n) ? cnt[gid] : 0;
    __syncthreads();
#pragma unroll
    for (int d = 1; d < 512; d <<= 1) {
        int add = (tid >= d) ? sm[tid - d] : 0;
        __syncthreads();
        sm[tid] += add;
        __syncthreads();
    }
    if (gid < n) incl[gid] = sm[tid];
    if (tid == 511) bsum[blockIdx.x] = sm[511];
}
__global__ void k_scan2(int* __restrict__ bsum, int nb) {
    __shared__ int sm[1024];
    int tid = threadIdx.x;
    sm[tid] = (tid < nb) ? bsum[tid] : 0;
    __syncthreads();
#pragma unroll
    for (int d = 1; d < 1024; d <<= 1) {
        int add = (tid >= d) ? sm[tid - d] : 0;
        __syncthreads();
        sm[tid] += add;
        __syncthreads();
    }
    if (tid < nb) bsum[tid] = sm[tid];
}
__global__ void k_scan3(const int* __restrict__ cnt, const int* __restrict__ incl,
                        const int* __restrict__ bsum, int* __restrict__ off,
                        int* __restrict__ cursor, int n) {
    int gid = blockIdx.x * 512 + threadIdx.x;
    if (gid >= n) return;
    int base = (blockIdx.x > 0) ? bsum[blockIdx.x - 1] : 0;
    int ex = base + incl[gid] - cnt[gid];
    off[gid] = ex;
    cursor[gid] = ex;
    if (gid == n - 1) off[n] = base + incl[gid];
}
__global__ void k_bin(const int* __restrict__ h, const int* __restrict__ r,
                      const int* __restrict__ t, int* __restrict__ cursor,
                      int* __restrict__ binh, int E) {
    int e = blockIdx.x * blockDim.x + threadIdx.x;
    if (e >= E) return;
    int seg = r[e] * NNODES + t[e];
    int pos = atomicAdd(&cursor[seg], 1);
    binh[pos] = h[e];
}

// WH for BOTH layers in one launch: [layer][z][n][k] = fp16 of W[k][n] (transposed)
__global__ void k_wt2(const float* __restrict__ W1, const float* __restrict__ root1,
                      const float* __restrict__ W2, const float* __restrict__ root2,
                      __half* __restrict__ dst) {
    int idx = blockIdx.x * blockDim.x + threadIdx.x;
    if (idx >= 2 * NZ * DIM * DIM) return;
    int zz = idx >> 14;
    int layer = zz / NZ, z = zz % NZ;
    int rem = idx & 16383;
    int n = rem >> 7, k = rem & 127;
    const float* src = (z < 8) ? ((layer ? W2 : W1) + ((size_t)z << 14))
                               : (layer ? root2 : root1);
    dst[idx] = __float2half_rn(src[k * DIM + n]);
}

__global__ void k_cvt16(const float2* __restrict__ in, uint32_t* __restrict__ out, int n2) {
    int i = blockIdx.x * blockDim.x + threadIdx.x;
    if (i < n2) {
        float2 v = in[i];
        __half2 hv = __floats2half2_rn(v.x, v.y);
        out[i] = *(uint32_t*)&hv;
    }
}

// ---------------- z-loop fp16 GEMM: for z in [0,9): Y_z = X_tile @ W_z ----------------
// One CTA owns a 128-row tile and all 9 outputs. A loaded once (full K=128);
// B double-buffered via cp.async across z. 8 warps 4x2; warp tile 32x64.
__global__ __launch_bounds__(256, 2) void k_gemm_z(
    const __half* __restrict__ X, const __half* __restrict__ WH,
    const float* __restrict__ bias, __half* __restrict__ Y,
    float* __restrict__ acc, int Nn)
{
    extern __shared__ uint32_t sm[];
    uint32_t* As = sm;                 // [128][KSTR]
    uint32_t* Bs = sm + A_SM;          // [2][128][KSTR]

    const int tid = threadIdx.x;
    const int wid = tid >> 5;
    const int lane = tid & 31;
    const int g = lane >> 2;
    const int q = lane & 3;
    const int warp_m = wid & 3;
    const int warp_n = wid >> 2;
    const int row0 = blockIdx.x * MTILE;

    const uint32_t abase = (uint32_t)__cvta_generic_to_shared(As);
    const uint32_t bbase = (uint32_t)__cvta_generic_to_shared(Bs);

    // ---- fill A tile (128 rows x 64 u32), 8 cp.async16 per thread ----
#pragma unroll
    for (int l = 0; l < 8; l++) {
        int lin = tid + 256 * l;
        int row = lin >> 4, seg = lin & 15;
        int gr = row0 + row;
        int ok = (gr < Nn) ? 16 : 0;
        int grc = (gr < Nn) ? gr : (Nn - 1);
        cp_async16(abase + (uint32_t)(row * KSTR + seg * 4) * 4,
                   X + (size_t)grc * DIM + seg * 8, ok);
    }
    CP_COMMIT();

    // ---- fill B for z=0 ----
    auto fill_B = [&](int buf, int z) {
        const __half* Bz = WH + ((size_t)z << 14);
        uint32_t base = bbase + (uint32_t)buf * B_SM * 4;
#pragma unroll
        for (int l = 0; l < 8; l++) {
            int lin = tid + 256 * l;
            int row = lin >> 4, seg = lin & 15;
            cp_async16(base + (uint32_t)(row * KSTR + seg * 4) * 4,
                       Bz + (size_t)row * DIM + seg * 8, 16);
        }
        CP_COMMIT();
    };
    fill_B(0, 0);

    const int ar = warp_m * 32 + g;
    const int bn = warp_n * 64 + g;

#pragma unroll 1
    for (int z = 0; z < NZ; z++) {
        if (z < NZ - 1) { fill_B((z + 1) & 1, z + 1); CP_WAIT1(); }
        else            { CP_WAIT0(); }
        __syncthreads();

        const uint32_t* B_ = Bs + (z & 1) * B_SM;

        float cfrag[2][8][4];
#pragma unroll
        for (int mt = 0; mt < 2; mt++)
#pragma unroll
            for (int nt = 0; nt < 8; nt++)
#pragma unroll
                for (int i = 0; i < 4; i++) cfrag[mt][nt][i] = 0.0f;

#pragma unroll
        for (int ks = 0; ks < 8; ks++) {
            const int ko = ks * 8 + q;
            uint32_t a[2][4];
#pragma unroll
            for (int mt = 0; mt < 2; mt++) {
                int base = (ar + mt * 16) * KSTR + ko;
                a[mt][0] = As[base];
                a[mt][1] = As[base + 8 * KSTR];
                a[mt][2] = As[base + 4];
                a[mt][3] = As[base + 8 * KSTR + 4];
            }
            uint32_t b[8][2];
#pragma unroll
            for (int nt = 0; nt < 8; nt++) {
                int base = (bn + nt * 8) * KSTR + ko;
                b[nt][0] = B_[base];
                b[nt][1] = B_[base + 4];
            }
#pragma unroll
            for (int mt = 0; mt < 2; mt++)
#pragma unroll
                for (int nt = 0; nt < 8; nt++)
                    mma_f16(cfrag[mt][nt], a[mt], b[nt]);
        }
        __syncthreads();   // all B_z reads done before its buffer is refilled at z+2

        // ---- epilogue for this z ----
        if (z < 8) {
            __half* C = Y + (size_t)z * Nn * DIM;
#pragma unroll
            for (int mt = 0; mt < 2; mt++)
#pragma unroll
                for (int half_ = 0; half_ < 2; half_++) {
                    int row = row0 + warp_m * 32 + mt * 16 + half_ * 8 + g;
                    if (row >= Nn) continue;
#pragma unroll
                    for (int nt = 0; nt < 8; nt++) {
                        int col = warp_n * 64 + nt * 8 + 2 * q;
                        __half2 hv = __floats2half2_rn(cfrag[mt][nt][half_ * 2 + 0],
                                                       cfrag[mt][nt][half_ * 2 + 1]);
                        *(uint32_t*)&C[(size_t)row * DIM + col] = *(uint32_t*)&hv;
                    }
                }
        } else {
#pragma unroll
            for (int mt = 0; mt < 2; mt++)
#pragma unroll
                for (int half_ = 0; half_ < 2; half_++) {
                    int row = row0 + warp_m * 32 + mt * 16 + half_ * 8 + g;
                    if (row >= Nn) continue;
#pragma unroll
                    for (int nt = 0; nt < 8; nt++) {
                        int col = warp_n * 64 + nt * 8 + 2 * q;
                        float2 v;
                        v.x = cfrag[mt][nt][half_ * 2 + 0] + bias[col];
                        v.y = cfrag[mt][nt][half_ * 2 + 1] + bias[col + 1];
                        *(float2*)&acc[(size_t)row * DIM + col] = v;
                    }
                }
        }
    }
}

// ---------------- aggregation: one warp per target node, atomic-free ----------------
// MODE 0: out = relu(acc + sum_r mean) -> fp16 A16.
// MODE 1: final layer -> block-reduced column mean accumulated into out[128].
template <int MODE>
__global__ __launch_bounds__(256) void k_agg(
    const __half* __restrict__ Y, const int* __restrict__ off,
    const int* __restrict__ binh, const float* __restrict__ accin,
    uint32_t* __restrict__ out16, float* __restrict__ outf)
{
    __shared__ float bsum[8][DIM];
    const int wid = threadIdx.x >> 5;
    const int lane = threadIdx.x & 31;
    const int t = blockIdx.x * 8 + wid;        // NNODES % 8 == 0 -> always valid

    float4 a4 = ((const float4*)(accin + (size_t)t * DIM))[lane];

#pragma unroll
    for (int rr = 0; rr < NREL; rr++) {
        int seg = rr * NNODES + t;
        int s = __ldg(&off[seg]);
        int e = __ldg(&off[seg + 1]);
        if (e > s) {
            float4 sum = make_float4(0.f, 0.f, 0.f, 0.f);
            const __half* Yr = Y + (size_t)rr * NNODES * DIM;
            for (int i = s; i < e; i++) {
                int hh = __ldg(&binh[i]);
                uint2 v = ((const uint2*)(Yr + (size_t)hh * DIM))[lane];
                __half2* hp = (__half2*)&v;
                float2 f0 = __half22float2(hp[0]);
                float2 f1 = __half22float2(hp[1]);
                sum.x += f0.x; sum.y += f0.y; sum.z += f1.x; sum.w += f1.y;
            }
            float w = 1.0f / (float)(e - s);
            a4.x += sum.x * w; a4.y += sum.y * w;
            a4.z += sum.z * w; a4.w += sum.w * w;
        }
    }

    if (MODE == 0) {
        __half2 h0 = __floats2half2_rn(fmaxf(a4.x, 0.f), fmaxf(a4.y, 0.f));
        __half2 h1 = __floats2half2_rn(fmaxf(a4.z, 0.f), fmaxf(a4.w, 0.f));
        uint2 o;
        o.x = *(uint32_t*)&h0;
        o.y = *(uint32_t*)&h1;
        ((uint2*)(out16 + (size_t)t * (DIM / 2)))[lane] = o;
    } else {
        bsum[wid][lane * 4 + 0] = a4.x;
        bsum[wid][lane * 4 + 1] = a4.y;
        bsum[wid][lane * 4 + 2] = a4.z;
        bsum[wid][lane * 4 + 3] = a4.w;
        __syncthreads();
        int c = threadIdx.x;
        if (c < DIM) {
            float s = 0.0f;
#pragma unroll
            for (int w2 = 0; w2 < 8; w2++) s += bsum[w2][c];
            atomicAdd(&outf[c], s * (1.0f / (float)NNODES));
        }
    }
}

__global__ void k_zero_out(float* __restrict__ out) { out[threadIdx.x] = 0.0f; }

// ---------------- launch ----------------
extern "C" void kernel_launch(void* const* d_in, const int* in_sizes, int n_in,
                              void* d_out, int out_size) {
    const int*   h     = (const int*)d_in[0];
    const int*   r     = (const int*)d_in[1];
    const int*   t     = (const int*)d_in[2];
    const float* x_emb = (const float*)d_in[3];
    const float* W1    = (const float*)d_in[4];
    const float* root1 = (const float*)d_in[5];
    const float* b1    = (const float*)d_in[6];
    const float* W2    = (const float*)d_in[7];
    const float* root2 = (const float*)d_in[8];
    const float* b2    = (const float*)d_in[9];
    float* out = (float*)d_out;

    __half *Y16, *A16, *WH;
    float *acc;
    int *cnt, *incl, *off, *cursor, *binh, *bsum;
    cudaGetSymbolAddress((void**)&Y16,    g_Y16);
    cudaGetSymbolAddress((void**)&acc,    g_acc);
    cudaGetSymbolAddress((void**)&A16,    g_A16);
    cudaGetSymbolAddress((void**)&WH,     g_WH);
    cudaGetSymbolAddress((void**)&cnt,    g_cnt);
    cudaGetSymbolAddress((void**)&incl,   g_incl);
    cudaGetSymbolAddress((void**)&off,    g_off);
    cudaGetSymbolAddress((void**)&cursor, g_cursor);
    cudaGetSymbolAddress((void**)&binh,   g_binh);
    cudaGetSymbolAddress((void**)&bsum,   g_bsum);

    const int E = NEDGES, Nn = NNODES;
    const int n2 = Nn * DIM / 2;
    const int agg_blocks = Nn / 8;   // 6250

    static bool attr_set = false;
    if (!attr_set) {
        cudaFuncSetAttribute(k_gemm_z, cudaFuncAttributeMaxDynamicSharedMemorySize, GEMM_SMEM);
        attr_set = true;
    }

    // [0] weights (both layers), [1] input cvt, [2] zero counters
    k_wt2<<<(2 * NZ * DIM * DIM + 255) / 256, 256>>>(W1, root1, W2, root2, WH);
    k_cvt16<<<(n2 + 255) / 256, 256>>>((const float2*)x_emb, (uint32_t*)A16, n2);
    k_zero_cnt<<<(SEG + 255) / 256, 256>>>(cnt, SEG);

    // [3] layer-1 GEMM (profiled launch)
    k_gemm_z<<<NRB, 256, GEMM_SMEM>>>(A16, WH, b1, Y16, acc, Nn);

    // CSR build
    k_count<<<(E + 255) / 256, 256>>>(r, t, cnt, E);
    k_scan1<<<NSCAN_BLK, 512>>>(cnt, incl, bsum, SEG);
    k_scan2<<<1, 1024>>>(bsum, NSCAN_BLK);
    k_scan3<<<NSCAN_BLK, 512>>>(cnt, incl, bsum, off, cursor, SEG);
    k_bin<<<(E + 255) / 256, 256>>>(h, r, t, cursor, binh, E);

    // layer-1 aggregation -> relu -> fp16 A16
    k_agg<0><<<agg_blocks, 256>>>(Y16, off, binh, acc, (uint32_t*)A16, nullptr);

    // layer-2 GEMM + aggregation fused with final column mean
    k_gemm_z<<<NRB, 256, GEMM_SMEM>>>(A16, WH + (size_t)NZ * DIM * DIM, b2, Y16, acc, Nn);
    k_zero_out<<<1, DIM>>>(out);
    k_agg<1><<<agg_blocks, 256>>>(Y16, off, binh, acc, nullptr, out);
}